// round 1
// baseline (speedup 1.0000x reference)
#include <cuda_runtime.h>
#include <cstdint>

// ---------------- static scratch (no allocs allowed) ----------------
#define NMAX 100352
#define EMAX 1700000

__device__ int   g_deg[NMAX];
__device__ int   g_off[NMAX + 1];
__device__ int   g_cur[NMAX];
__device__ int   g_csr[EMAX];
__device__ float g_cnt[NMAX];
__device__ float g_bufA[(size_t)NMAX * 256];
__device__ float g_bufB[(size_t)NMAX * 256];
__device__ float g_meanb[(size_t)NMAX * 256];

// ---------------- CSR build ----------------
__global__ void k_zero(int n) {
    int i = blockIdx.x * blockDim.x + threadIdx.x;
    if (i < n) g_deg[i] = 0;
}

__global__ void k_hist(const int* __restrict__ dst, int E) {
    int e = blockIdx.x * blockDim.x + threadIdx.x;
    if (e < E) atomicAdd(&g_deg[dst[e]], 1);
}

// single block, 1024 threads: exclusive scan of deg -> off, also cur, cnt
__global__ void k_scan(int n) {
    __shared__ int part[1024];
    int t = threadIdx.x;
    int chunk = (n + 1023) / 1024;
    int beg = t * chunk;
    int end = min(beg + chunk, n);
    int s = 0;
    for (int i = beg; i < end; i++) s += g_deg[i];
    part[t] = s;
    __syncthreads();
    // inclusive Hillis-Steele scan
    for (int off = 1; off < 1024; off <<= 1) {
        int v = (t >= off) ? part[t - off] : 0;
        __syncthreads();
        part[t] += v;
        __syncthreads();
    }
    int run = (t == 0) ? 0 : part[t - 1];
    for (int i = beg; i < end; i++) {
        int d = g_deg[i];
        g_off[i] = run;
        g_cur[i] = run;
        g_cnt[i] = (d > 0) ? (float)d : 1.0f;
        run += d;
    }
    if (end == n) g_off[n] = run;
}

__global__ void k_scatter(const int* __restrict__ src, const int* __restrict__ dst, int E) {
    int e = blockIdx.x * blockDim.x + threadIdx.x;
    if (e < E) {
        int p = atomicAdd(&g_cur[dst[e]], 1);
        g_csr[p] = src[e];
    }
}

// canonicalize segment order (determinism across replays): insertion sort per node
__global__ void k_sortseg(int n) {
    int i = blockIdx.x * blockDim.x + threadIdx.x;
    if (i >= n) return;
    int b = g_off[i], e = g_off[i + 1];
    for (int j = b + 1; j < e; j++) {
        int v = g_csr[j];
        int k = j - 1;
        while (k >= b && g_csr[k] > v) { g_csr[k + 1] = g_csr[k]; k--; }
        g_csr[k + 1] = v;
    }
}

// ---------------- mean aggregation: one warp per node ----------------
template <int D>
__global__ void k_agg(const float* __restrict__ x, float* __restrict__ meanp, int n) {
    int gw = (blockIdx.x * blockDim.x + threadIdx.x) >> 5;
    int lane = threadIdx.x & 31;
    if (gw >= n) return;
    int b = g_off[gw], e = g_off[gw + 1];
    constexpr int IT = D / 128;
    float4 acc[IT];
#pragma unroll
    for (int it = 0; it < IT; it++) acc[it] = make_float4(0.f, 0.f, 0.f, 0.f);
    for (int j = b; j < e; j++) {
        const float4* row = (const float4*)(x + (size_t)g_csr[j] * D);
#pragma unroll
        for (int it = 0; it < IT; it++) {
            float4 v = row[lane + it * 32];
            acc[it].x += v.x; acc[it].y += v.y; acc[it].z += v.z; acc[it].w += v.w;
        }
    }
    float inv = 1.0f / g_cnt[gw];
    float4* mo = (float4*)(meanp + (size_t)gw * D);
#pragma unroll
    for (int it = 0; it < IT; it++) {
        float4 v = acc[it];
        v.x *= inv; v.y *= inv; v.z *= inv; v.w *= inv;
        mo[lane + it * 32] = v;
    }
}

// ---------------- fused dual-GEMM + bias + LayerNorm + ReLU ----------------
// C[n, DOUT] = LNReLU( mean @ W0 + x @ W1 + b )
// Block: 256 threads, tile 64 rows x DOUT cols. Warp w owns rows w*8..w*8+7
// entirely (8 rows x TN cols-per-lane), enabling warp-shuffle LayerNorm.
template <int DIN, int DOUT>
__launch_bounds__(256)
__global__ void k_gemm_ln(const float* __restrict__ A0, const float* __restrict__ A1,
                          const float* __restrict__ W0, const float* __restrict__ W1,
                          const float* __restrict__ bias, const float* __restrict__ gamma,
                          const float* __restrict__ beta, float* __restrict__ out, int n) {
    constexpr int TN = DOUT / 32;
    __shared__ float As[64][16];
    __shared__ float Ws[16][DOUT];

    int t = threadIdx.x;
    int lane = t & 31;
    int warp = t >> 5;
    int row0 = blockIdx.x * 64;

    float acc[8][TN];
#pragma unroll
    for (int m = 0; m < 8; m++)
#pragma unroll
        for (int j = 0; j < TN; j++) acc[m][j] = 0.f;

    for (int ph = 0; ph < 2; ph++) {
        const float* A = ph ? A1 : A0;
        const float* W = ph ? W1 : W0;
        for (int k0 = 0; k0 < DIN; k0 += 16) {
            __syncthreads();
            {   // A tile: 64x16, one float4 per thread
                int ar = t >> 2;
                int ac = (t & 3) * 4;
                int gr = row0 + ar;
                float4 v = make_float4(0.f, 0.f, 0.f, 0.f);
                if (gr < n) v = *(const float4*)(A + (size_t)gr * DIN + k0 + ac);
                *(float4*)&As[ar][ac] = v;
            }
            {   // W tile: 16 x DOUT
                constexpr int NC4 = DOUT / 4;
#pragma unroll
                for (int i = 0; i < 16 * NC4 / 256; i++) {
                    int idx = t + i * 256;
                    int wrw = idx / NC4;
                    int wc = (idx % NC4) * 4;
                    *(float4*)&Ws[wrw][wc] = *(const float4*)(W + (size_t)(k0 + wrw) * DOUT + wc);
                }
            }
            __syncthreads();
#pragma unroll
            for (int kk = 0; kk < 16; kk++) {
                float a[8];
#pragma unroll
                for (int m = 0; m < 8; m++) a[m] = As[warp * 8 + m][kk];
                float wv[TN];
#pragma unroll
                for (int j = 0; j < TN; j++) wv[j] = Ws[kk][lane + 32 * j];
#pragma unroll
                for (int m = 0; m < 8; m++)
#pragma unroll
                    for (int j = 0; j < TN; j++) acc[m][j] = fmaf(a[m], wv[j], acc[m][j]);
            }
        }
    }

    // epilogue: +bias, LayerNorm over DOUT (warp shuffles), scale/shift, ReLU
    float bia[TN], ga[TN], bt[TN];
#pragma unroll
    for (int j = 0; j < TN; j++) {
        int c = lane + 32 * j;
        bia[j] = bias[c];
        ga[j] = gamma[c];
        bt[j] = beta[c];
    }
#pragma unroll
    for (int m = 0; m < 8; m++) {
        int row = row0 + warp * 8 + m;
        float v[TN];
        float s = 0.f, ss = 0.f;
#pragma unroll
        for (int j = 0; j < TN; j++) {
            v[j] = acc[m][j] + bia[j];
            s += v[j];
            ss += v[j] * v[j];
        }
#pragma unroll
        for (int o = 16; o; o >>= 1) {
            s += __shfl_xor_sync(0xffffffffu, s, o);
            ss += __shfl_xor_sync(0xffffffffu, ss, o);
        }
        float mu = s * (1.0f / DOUT);
        float var = ss * (1.0f / DOUT) - mu * mu;
        float rs = rsqrtf(var + 1e-5f);
        if (row < n) {
#pragma unroll
            for (int j = 0; j < TN; j++) {
                float ov = fmaxf((v[j] - mu) * rs * ga[j] + bt[j], 0.f);
                out[(size_t)row * DOUT + lane + 32 * j] = ov;
            }
        }
    }
}

// ---------------- final layer: DIN=128 -> DOUT=9, no LN ----------------
__global__ void k_out(const float* __restrict__ meanp, const float* __restrict__ x,
                      const float* __restrict__ wm, const float* __restrict__ wr,
                      const float* __restrict__ bias, float* __restrict__ out, int n) {
    __shared__ float swm[128 * 9];
    __shared__ float swr[128 * 9];
    __shared__ float sb[9];
    for (int i = threadIdx.x; i < 128 * 9; i += blockDim.x) {
        swm[i] = wm[i];
        swr[i] = wr[i];
    }
    if (threadIdx.x < 9) sb[threadIdx.x] = bias[threadIdx.x];
    __syncthreads();

    int gw = (blockIdx.x * blockDim.x + threadIdx.x) >> 5;
    int lane = threadIdx.x & 31;
    if (gw >= n) return;

    float4 am = ((const float4*)(meanp + (size_t)gw * 128))[lane];
    float4 ax = ((const float4*)(x + (size_t)gw * 128))[lane];
    float a4[4] = {am.x, am.y, am.z, am.w};
    float x4[4] = {ax.x, ax.y, ax.z, ax.w};

    float o[9];
#pragma unroll
    for (int j = 0; j < 9; j++) o[j] = 0.f;
#pragma unroll
    for (int q = 0; q < 4; q++) {
        int k = lane * 4 + q;
#pragma unroll
        for (int j = 0; j < 9; j++)
            o[j] += a4[q] * swm[k * 9 + j] + x4[q] * swr[k * 9 + j];
    }
#pragma unroll
    for (int j = 0; j < 9; j++)
#pragma unroll
        for (int s = 16; s; s >>= 1) o[j] += __shfl_xor_sync(0xffffffffu, o[j], s);
    if (lane < 9) out[(size_t)gw * 9 + lane] = o[lane] + sb[lane];
}

// ---------------- launch ----------------
extern "C" void kernel_launch(void* const* d_in, const int* in_sizes, int n_in,
                              void* d_out, int out_size) {
    const float* z = (const float*)d_in[0];
    const int* ei = (const int*)d_in[1];
    const float* wm1 = (const float*)d_in[2];
    const float* wr1 = (const float*)d_in[3];
    const float* b1 = (const float*)d_in[4];
    const float* g1 = (const float*)d_in[5];
    const float* be1 = (const float*)d_in[6];
    const float* wm2 = (const float*)d_in[7];
    const float* wr2 = (const float*)d_in[8];
    const float* b2 = (const float*)d_in[9];
    const float* g2 = (const float*)d_in[10];
    const float* be2 = (const float*)d_in[11];
    const float* wm3 = (const float*)d_in[12];
    const float* wr3 = (const float*)d_in[13];
    const float* b3 = (const float*)d_in[14];
    const float* g3 = (const float*)d_in[15];
    const float* be3 = (const float*)d_in[16];
    const float* wm4 = (const float*)d_in[17];
    const float* wr4 = (const float*)d_in[18];
    const float* b4 = (const float*)d_in[19];

    int N = in_sizes[0] / 128;
    int E = in_sizes[1] / 2;
    const int* src = ei;
    const int* dst = ei + E;

    float *bufA, *bufB, *meanb;
    void* p;
    cudaGetSymbolAddress(&p, g_bufA);  bufA = (float*)p;
    cudaGetSymbolAddress(&p, g_bufB);  bufB = (float*)p;
    cudaGetSymbolAddress(&p, g_meanb); meanb = (float*)p;

    // CSR build (deterministic after segment sort)
    k_zero<<<(N + 255) / 256, 256>>>(N);
    k_hist<<<(E + 255) / 256, 256>>>(dst, E);
    k_scan<<<1, 1024>>>(N);
    k_scatter<<<(E + 255) / 256, 256>>>(src, dst, E);
    k_sortseg<<<(N + 255) / 256, 256>>>(N);

    int aggBlocks = (N + 7) / 8;       // warp per node, 256 thr/block
    int gemmBlocks = (N + 63) / 64;

    // Layer 1: 128 -> 256
    k_agg<128><<<aggBlocks, 256>>>(z, meanb, N);
    k_gemm_ln<128, 256><<<gemmBlocks, 256>>>(meanb, z, wm1, wr1, b1, g1, be1, bufA, N);
    // Layer 2: 256 -> 256
    k_agg<256><<<aggBlocks, 256>>>(bufA, meanb, N);
    k_gemm_ln<256, 256><<<gemmBlocks, 256>>>(meanb, bufA, wm2, wr2, b2, g2, be2, bufB, N);
    // Layer 3: 256 -> 128
    k_agg<256><<<aggBlocks, 256>>>(bufB, meanb, N);
    k_gemm_ln<256, 128><<<gemmBlocks, 256>>>(meanb, bufB, wm3, wr3, b3, g3, be3, bufA, N);
    // Layer 4: 128 -> 9 (no LN)
    k_agg<128><<<aggBlocks, 256>>>(bufA, meanb, N);
    k_out<<<aggBlocks, 256>>>(meanb, bufA, wm4, wr4, b4, (float*)d_out, N);
}